// round 10
// baseline (speedup 1.0000x reference)
#include <cuda_runtime.h>

// ---------------- problem dims (fixed by the dataset) ----------------
#define BATCH   2
#define C_IN    256
#define HH      40
#define WW      40
#define CMID    64     // compressed channels
#define CK      100    // k2 * S^2 encoder output channels
#define KK      25     // k2
#define HPAD    44     // xT padded (halo 2)
#define CPH     42     // comp padded (halo 1)

typedef unsigned long long u64;

__device__ __forceinline__ u64 dup2f(float x) {
    u64 r; asm("mov.b64 %0,{%1,%1};" : "=l"(r) : "f"(x)); return r;
}
__device__ __forceinline__ void fma2(u64& d, u64 a, u64 b) {
    asm("fma.rn.f32x2 %0,%1,%2,%0;" : "+l"(d) : "l"(a), "l"(b));
}

// ---------------- scratch (zero-initialized at module load; halos stay 0) ----------------
__device__ __align__(16) float  g_xT  [BATCH * HPAD * HPAD * C_IN];  // x NHWC, 2-px zero halo
__device__ __align__(16) float  g_comp[BATCH * CPH  * CPH  * CMID];  // compressed NHWC, halo 1
__device__ __align__(16) float  g_wt  [9 * CMID * CK];               // w_enc [tap][ci][o]
__device__ __align__(16) float4 g_soft[BATCH * HH * WW * KK];        // softmax wts [b][p][k]{d}

// ---------------- A': 1x1 GEMM + fused x transpose (blocks 0..159) + wenc prep (160..339) ----
// GEMM block: 20 px x 64 outputs, ALL of w_comp resident in smem (loaded once),
// x streamed in 4 K-chunks. 320 threads: px = t%20, 4 outs each (o0 = (t/20)*4).
#define AW_STRIDE 68
#define AX_STRIDE 21
#define SMEM_A_BYTES ((C_IN * AW_STRIDE + 64 * AX_STRIDE) * (int)sizeof(float))

__global__ void __launch_bounds__(320) A_kernel(const float* __restrict__ x,
                                                const float* __restrict__ wcomp,
                                                const float* __restrict__ wenc) {
    extern __shared__ float sm[];
    float* w_s = sm;                        // [c 256][o 64] stride 68
    float* x_s = sm + C_IN * AW_STRIDE;     // [c 64][px 20] stride 21

    const int t   = threadIdx.x;
    const int blk = blockIdx.x;

    if (blk >= 160) {                       // wenc prep: g_wt[tap][ci][o] = wenc[o][ci][tap]
        int j = (blk - 160) * 320 + t;
        if (j < 9 * CMID * CK) {
            int tap = j / (CMID * CK);
            int r   = j % (CMID * CK);
            int ci  = r / CK;
            int o   = r % CK;
            g_wt[j] = wenc[o * (CMID * 9) + ci * 9 + tap];
        }
        return;
    }

    const int g  = blk * 20;                // global pixel (incl batch), 20-aligned
    const int b  = g / (HH * WW);
    const int p0 = g % (HH * WW);

    // load ALL of w_comp transposed: w_s[c][o] = wcomp[o][c] (coalesced LDG along c)
    for (int i = t; i < CMID * C_IN; i += 320) {
        int o = i >> 8, c = i & 255;
        w_s[c * AW_STRIDE + o] = wcomp[o * C_IN + c];
    }

    const int px = t % 20;
    const int o0 = (t / 20) * 4;            // 4 consecutive outputs

    u64 acc0 = 0, acc1 = 0;

    for (int c0 = 0; c0 < C_IN; c0 += 64) {
        __syncthreads();
        // x chunk [64 c][20 px], coalesced along px
        #pragma unroll
        for (int r = 0; r < 4; r++) {
            int idx = t + r * 320;
            int cl = idx / 20, pl = idx % 20;
            x_s[cl * AX_STRIDE + pl] =
                x[((size_t)(b * C_IN) + c0 + cl) * (HH * WW) + p0 + pl];
        }
        __syncthreads();
        // emit transposed x to g_xT (coalesced along channels)
        #pragma unroll
        for (int r = 0; r < 4; r++) {
            int idx = t + r * 320;
            int cl = idx & 63, pl = idx >> 6;
            int pix = p0 + pl;
            int hs = pix / WW, ws = pix % WW;
            g_xT[((size_t)(b * HPAD + hs + 2) * HPAD + (ws + 2)) * C_IN + c0 + cl] =
                x_s[cl * AX_STRIDE + pl];
        }
        // GEMM chunk
        #pragma unroll 16
        for (int c = 0; c < 64; c++) {
            u64 xx = dup2f(x_s[c * AX_STRIDE + px]);
            ulonglong2 w = *(const ulonglong2*)&w_s[(c0 + c) * AW_STRIDE + o0];
            fma2(acc0, xx, w.x);
            fma2(acc1, xx, w.y);
        }
    }

    const int pix = p0 + px;
    const int hs = pix / WW, ws = pix % WW;
    float* dst = &g_comp[((size_t)(b * CPH + hs + 1) * CPH + (ws + 1)) * CMID + o0];
    *(ulonglong2*)dst = make_ulonglong2(acc0, acc1);
}

// ---------------- K2: 3x3 encoder conv (100 ch) + fused softmax (R8, single comp buffer) ----
// 160 blocks = b(2) x rowpair(20) x colseg(4); 256 threads.
#define CS_STRIDE 66

__global__ void __launch_bounds__(256) K2_encoder() {
    __shared__ float  comp_s[48 * CS_STRIDE];   // 12.7 KB
    __shared__ float  kk[20 * CK];              // kern logits [px][100] (8 KB)
    __shared__ float4 ss[20 * KK];              // softmax out [pl][k]{d0..d3} (8 KB)

    const int t    = threadIdx.x;
    const int blk  = blockIdx.x;
    const int b    = blk / 80;
    const int rem  = blk % 80;
    const int r0   = (rem / 4) * 2;             // kern rows r0, r0+1
    const int cs0  = (rem % 4) * 10;            // kern cols cs0..cs0+9

    // comp tile: padded rows r0..r0+3, cols cs0..cs0+11
    #pragma unroll
    for (int r = 0; r < 6; r++) {
        int i  = t + r * 256;
        int px = i >> 5, c2 = i & 31;
        int dr = px / 12, dc = px % 12;
        *(float2*)&comp_s[px * CS_STRIDE + c2 * 2] =
            *(const float2*)&g_comp[((size_t)(b * CPH + r0 + dr) * CPH + cs0 + dc) * CMID + c2 * 2];
    }
    __syncthreads();

    const int og = t / 5;                       // 0..51 (active < 50)
    const int cp = t % 5;

    u64 a00 = 0, a01 = 0, a10 = 0, a11 = 0;
    if (og < 50) {
        const float* wt0 = &g_wt[og * 2];
        #pragma unroll
        for (int tap = 0; tap < 9; tap++) {
            const float* xb = &comp_s[((tap / 3) * 12 + 2 * cp + (tap % 3)) * CS_STRIDE];
            const float* wt = wt0 + tap * (CMID * CK);
            #pragma unroll 8
            for (int ci = 0; ci < CMID; ci += 2) {
                float2 x00 = *(const float2*)&xb[ci];
                float2 x01 = *(const float2*)&xb[CS_STRIDE + ci];
                float2 x10 = *(const float2*)&xb[12 * CS_STRIDE + ci];
                float2 x11 = *(const float2*)&xb[13 * CS_STRIDE + ci];
                u64 w0 = *(const u64*)&wt[ci * CK];
                u64 w1 = *(const u64*)&wt[ci * CK + CK];
                fma2(a00, dup2f(x00.x), w0); fma2(a01, dup2f(x01.x), w0);
                fma2(a10, dup2f(x10.x), w0); fma2(a11, dup2f(x11.x), w0);
                fma2(a00, dup2f(x00.y), w1); fma2(a01, dup2f(x01.y), w1);
                fma2(a10, dup2f(x10.y), w1); fma2(a11, dup2f(x11.y), w1);
            }
        }
    }
    __syncthreads();
    if (og < 50) {                              // stage logits: px = dr*10 + col
        *(u64*)&kk[(2 * cp)      * CK + 2 * og] = a00;
        *(u64*)&kk[(2 * cp + 1)  * CK + 2 * og] = a01;
        *(u64*)&kk[(10 + 2 * cp) * CK + 2 * og] = a10;
        *(u64*)&kk[(11 + 2 * cp) * CK + 2 * og] = a11;
    }
    __syncthreads();

    // ---- 80 softmaxes: (20 kern px) x (sh, sw) ----
    const int wid = t >> 5, lane = t & 31;
    for (int s = wid; s < 80; s += 8) {
        const int px = s >> 2, q = s & 3;
        const int sh = q >> 1, sw = q & 1;
        const int dr = px / 10, wk = cs0 + px % 10;
        float v = -3.0e38f;
        if (lane < KK)
            v = kk[px * CK + lane * 4 + sh * 2 + sw];
        float m = v;
        #pragma unroll
        for (int off = 16; off; off >>= 1)
            m = fmaxf(m, __shfl_xor_sync(0xffffffffu, m, off));
        float e = (lane < KK) ? __expf(v - m) : 0.f;
        float su = e;
        #pragma unroll
        for (int off = 16; off; off >>= 1)
            su += __shfl_xor_sync(0xffffffffu, su, off);
        const int pl = (2 * dr + sh) * 5 + ((wk >> 1) - (cs0 >> 1));
        const int d  = 2 * (wk & 1) + sw;
        if (lane < KK)
            ((float*)&ss[pl * KK + lane])[d] = e / su;
    }
    __syncthreads();

    // ---- store g_soft: 500 f4, coalesced ----
    #pragma unroll
    for (int r = 0; r < 2; r++) {
        int f = t + r * 256;
        if (f < 500) {
            int pl = f / KK, k = f % KK;
            int hu = 2 * r0 + pl / 5;
            int p  = 20 * hu + (cs0 >> 1) + pl % 5;
            g_soft[((size_t)b * (HH * WW) + p) * KK + k] = ss[f];
        }
    }
}

// ---------------- K3: reassembly (R8 verbatim) ----------------
// 640 blocks x 256 threads: 5 source px per block, thread = 1 channel.
#define ST_STRIDE 24

__global__ void __launch_bounds__(256) K3_reassemble(float* __restrict__ out) {
    __shared__ float4 sk[5 * KK];           // softmax weights (2 KB)
    __shared__ float  st[256 * ST_STRIDE];  // output staging (24.6 KB)

    const int t   = threadIdx.x;
    const int blk = blockIdx.x;
    const int b   = blk / 320;
    const int p0  = (blk % 320) * 5;

    const int hu    = p0 / 20, pm0 = p0 % 20;
    const int hsrc  = p0 / WW, wsrc0 = p0 % WW;

    if (t < 125)
        sk[t] = g_soft[((size_t)b * (HH * WW) + p0) * KK + t];

    // window loads: 5 rows x 9 cols, all in flight
    const float* xb = &g_xT[((size_t)(b * HPAD + hsrc) * HPAD + wsrc0) * C_IN + t];
    float xw[45];
    #pragma unroll
    for (int r = 0; r < 5; r++)
        #pragma unroll
        for (int c = 0; c < 9; c++)
            xw[r * 9 + c] = xb[(r * HPAD + c) * C_IN];
    __syncthreads();

    #pragma unroll
    for (int i = 0; i < 5; i++) {
        const ulonglong2* skp = (const ulonglong2*)&sk[i * KK];
        u64 a01 = 0, a23 = 0;
        #pragma unroll
        for (int k = 0; k < 25; k++) {
            u64 xx = dup2f(xw[(k / 5) * 9 + i + (k % 5)]);
            ulonglong2 w = skp[k];
            fma2(a01, xx, w.x);
            fma2(a23, xx, w.y);
        }
        *(u64*)&st[t * ST_STRIDE + i * 4]     = a01;
        *(u64*)&st[t * ST_STRIDE + i * 4 + 2] = a23;
    }
    __syncthreads();

    const size_t obase = ((size_t)(b * C_IN) * (2 * HH) + hu) * (2 * WW) + pm0 * 4;
    #pragma unroll
    for (int j = 0; j < 5; j++) {
        int f  = t + j * 256;
        int ch = f / 5, w4 = f % 5;
        float4 v = *(const float4*)&st[ch * ST_STRIDE + w4 * 4];
        *(float4*)&out[obase + (size_t)ch * (4 * HH * WW) + w4 * 4] = v;
    }
}

// ---------------- launch ----------------
extern "C" void kernel_launch(void* const* d_in, const int* in_sizes, int n_in,
                              void* d_out, int out_size) {
    const float* x     = (const float*)d_in[0];
    const float* wcomp = (const float*)d_in[1];
    const float* wenc  = (const float*)d_in[2];
    float* out = (float*)d_out;

    cudaFuncSetAttribute(A_kernel,
                         cudaFuncAttributeMaxDynamicSharedMemorySize, SMEM_A_BYTES);

    A_kernel<<<160 + (9 * CMID * CK + 319) / 320, 320, SMEM_A_BYTES>>>(x, wcomp, wenc);
    K2_encoder<<<160, 256>>>();
    K3_reassemble<<<640, 256>>>(out);
}

// round 11
// speedup vs baseline: 1.2845x; 1.2845x over previous
#include <cuda_runtime.h>
#include <cuda_pipeline.h>

// ---------------- problem dims (fixed by the dataset) ----------------
#define BATCH   2
#define C_IN    256
#define HH      40
#define WW      40
#define CMID    64     // compressed channels
#define CK      100    // k2 * S^2 encoder output channels
#define KK      25     // k2
#define HPAD    44     // xT padded (halo 2)
#define CPH     42     // comp padded (halo 1)

typedef unsigned long long u64;

__device__ __forceinline__ u64 dup2f(float x) {
    u64 r; asm("mov.b64 %0,{%1,%1};" : "=l"(r) : "f"(x)); return r;
}
__device__ __forceinline__ void fma2(u64& d, u64 a, u64 b) {
    asm("fma.rn.f32x2 %0,%1,%2,%0;" : "+l"(d) : "l"(a), "l"(b));
}

// ---------------- scratch (zero-initialized at module load; halos stay 0) ----------------
__device__ __align__(16) float g_xT  [BATCH * HPAD * HPAD * C_IN];   // x NHWC, 2-px zero halo
__device__ __align__(16) float g_comp[BATCH * CPH  * CPH  * CMID];   // compressed NHWC, 1-px halo
__device__ __align__(16) float g_kern[BATCH * HH * WW * CK];         // encoder conv out, NHWC
__device__ __align__(16) float g_wt  [9 * CMID * CK];                // w_enc transposed [tap][ci][o]

// ---------------- stage A (R2 verbatim): 1x1 GEMM + fused x transpose + wenc prep ----------------
// blocks 0..99: GEMM (32 pixels x 64 outputs each). blocks 100..324: wenc transpose.
#define WS_STRIDE 68
#define XS_STRIDE 33
#define SMEM_A_BYTES ((C_IN * WS_STRIDE + 64 * XS_STRIDE) * (int)sizeof(float))

__global__ void stageA_compress(const float* __restrict__ x,
                                const float* __restrict__ wcomp,
                                const float* __restrict__ wenc) {
    extern __shared__ float sm[];
    float* w_s = sm;                       // [c][o] padded stride 68
    float* x_s = sm + C_IN * WS_STRIDE;    // [c_l][pix] padded stride 33

    const int t   = threadIdx.x;
    const int blk = blockIdx.x;

    if (blk >= 100) {                      // w_enc transpose: (100,64,3,3) -> [tap][ci][o]
        int i = (blk - 100) * 256 + t;
        if (i < 9 * CMID * CK) {
            int tap  = i / (CMID * CK);
            int rest = i % (CMID * CK);
            int ci   = rest / CK;
            int o    = rest % CK;
            g_wt[i] = wenc[o * (CMID * 9) + ci * 9 + tap];
        }
        return;
    }

    const int b    = blk / 50;
    const int pix0 = (blk % 50) * 32;

    // load all of w_comp (64 x 256), transposed to [c][o]
    for (int i = t; i < CMID * C_IN; i += 256) {
        int o = i >> 8, c = i & 255;
        w_s[c * WS_STRIDE + o] = wcomp[i];
    }

    u64 acc[4] = {0ull, 0ull, 0ull, 0ull};
    const int pix_l = t & 31;              // warp spans 32 pixels (x coalesced)
    const int o0    = (t >> 5) << 3;       // warp shares o0 (w broadcast)

    for (int c0 = 0; c0 < C_IN; c0 += 64) {
        __syncthreads();
        #pragma unroll
        for (int r = 0; r < 8; r++) {
            int idx = t + r * 256;
            int cl = idx >> 5, pl = idx & 31;
            x_s[cl * XS_STRIDE + pl] =
                x[(size_t)(b * C_IN + c0 + cl) * (HH * WW) + pix0 + pl];
        }
        __syncthreads();
        // emit transposed x to g_xT (coalesced along channels)
        #pragma unroll
        for (int r = 0; r < 8; r++) {
            int idx = t + r * 256;
            int cl = idx & 63, pl = idx >> 6;
            int pix = pix0 + pl;
            int hs = pix / WW, ws = pix % WW;
            g_xT[((size_t)(b * HPAD + hs + 2) * HPAD + (ws + 2)) * C_IN + c0 + cl] =
                x_s[cl * XS_STRIDE + pl];
        }
        #pragma unroll 16
        for (int c = 0; c < 64; c++) {
            float xv = x_s[c * XS_STRIDE + pix_l];
            u64 xx = dup2f(xv);
            ulonglong2 wa = *(const ulonglong2*)&w_s[(c0 + c) * WS_STRIDE + o0];
            ulonglong2 wb = *(const ulonglong2*)&w_s[(c0 + c) * WS_STRIDE + o0 + 4];
            fma2(acc[0], xx, wa.x); fma2(acc[1], xx, wa.y);
            fma2(acc[2], xx, wb.x); fma2(acc[3], xx, wb.y);
        }
    }

    const int pix = pix0 + pix_l;
    const int hs = pix / WW, ws = pix % WW;
    float* dst = &g_comp[((size_t)(b * CPH + hs + 1) * CPH + (ws + 1)) * CMID + o0];
    *(ulonglong2*)(dst)     = make_ulonglong2(acc[0], acc[1]);
    *(ulonglong2*)(dst + 4) = make_ulonglong2(acc[2], acc[3]);
}

// ---------------- stage B (R2 verbatim): 3x3 encoder conv (64 -> 100 ch) ----------------
#define CS_STRIDE 66
#define B_WBUF    (CMID * CK)                 // 6400 floats per tap
#define SMEM_B_BYTES ((2 * B_WBUF + 48 * CS_STRIDE) * (int)sizeof(float))

__global__ void __launch_bounds__(128) stageB_encoder() {
    extern __shared__ float smB[];
    float* wbuf   = smB;                       // [2][6400]
    float* comp_s = smB + 2 * B_WBUF;          // [48 px][66]

    const int t   = threadIdx.x;
    const int blk = blockIdx.x;
    const int b   = blk / 80;
    const int rem = blk % 80;
    const int h0  = (rem / 4) * 2;
    const int ws0 = (rem % 4) * 10;

    for (int i = t; i < 48 * CMID; i += 128) {
        int pxl = i >> 6, ci = i & 63;
        comp_s[pxl * CS_STRIDE + ci] =
            g_comp[((size_t)(b * CPH + h0 + pxl / 12) * CPH + ws0 + pxl % 12) * CMID + ci];
    }

    for (int i = t; i < B_WBUF / 4; i += 128)
        __pipeline_memcpy_async(&wbuf[i * 4], &g_wt[i * 4], 16);
    __pipeline_commit();

    const int og  = t / 5;          // 0..24 (t<125 active)
    const int pxg = t % 5;
    const bool active = (t < 125);

    u64 a00 = 0, a01 = 0, a10 = 0, a11 = 0;   // row0 col0/col1: {o0,o1},{o2,o3} packed per px
    u64 b00 = 0, b01 = 0, b10 = 0, b11 = 0;   // row1

    for (int tap = 0; tap < 9; tap++) {
        if (tap < 8) {
            float* dst = &wbuf[((tap + 1) & 1) * B_WBUF];
            const float* src = &g_wt[(tap + 1) * B_WBUF];
            for (int i = t; i < B_WBUF / 4; i += 128)
                __pipeline_memcpy_async(&dst[i * 4], &src[i * 4], 16);
            __pipeline_commit();
            __pipeline_wait_prior(1);
        } else {
            __pipeline_wait_prior(0);
        }
        __syncthreads();

        if (active) {
            const float* ws = &wbuf[(tap & 1) * B_WBUF];
            const int dh = tap / 3, dw = tap % 3;
            const float* p00 = &comp_s[(dh * 12 + 2 * pxg + dw) * CS_STRIDE];
            const float* p01 = p00 + CS_STRIDE;
            const float* p10 = p00 + 12 * CS_STRIDE;
            const float* p11 = p10 + CS_STRIDE;
            #pragma unroll 8
            for (int ci = 0; ci < CMID; ci += 2) {
                float2 x00 = *(const float2*)&p00[ci];
                float2 x01 = *(const float2*)&p01[ci];
                float2 x10 = *(const float2*)&p10[ci];
                float2 x11 = *(const float2*)&p11[ci];
                ulonglong2 w0 = *(const ulonglong2*)&ws[ci * CK + og * 4];
                ulonglong2 w1 = *(const ulonglong2*)&ws[(ci + 1) * CK + og * 4];
                u64 d;
                d = dup2f(x00.x); fma2(a00, d, w0.x); fma2(a01, d, w0.y);
                d = dup2f(x01.x); fma2(a10, d, w0.x); fma2(a11, d, w0.y);
                d = dup2f(x10.x); fma2(b00, d, w0.x); fma2(b01, d, w0.y);
                d = dup2f(x11.x); fma2(b10, d, w0.x); fma2(b11, d, w0.y);
                d = dup2f(x00.y); fma2(a00, d, w1.x); fma2(a01, d, w1.y);
                d = dup2f(x01.y); fma2(a10, d, w1.x); fma2(a11, d, w1.y);
                d = dup2f(x10.y); fma2(b00, d, w1.x); fma2(b01, d, w1.y);
                d = dup2f(x11.y); fma2(b10, d, w1.x); fma2(b11, d, w1.y);
            }
        }
        __syncthreads();
    }

    if (active) {
        const int c0 = ws0 + 2 * pxg;
        float* r0 = &g_kern[((size_t)(b * HH + h0) * WW + c0) * CK + og * 4];
        float* r1 = &g_kern[((size_t)(b * HH + h0 + 1) * WW + c0) * CK + og * 4];
        *(ulonglong2*)(r0)      = make_ulonglong2(a00, a01);
        *(ulonglong2*)(r0 + CK) = make_ulonglong2(a10, a11);
        *(ulonglong2*)(r1)      = make_ulonglong2(b00, b01);
        *(ulonglong2*)(r1 + CK) = make_ulonglong2(b10, b11);
    }
}

// ---------------- stage C (R7 verbatim): sliding-window reassembly, coalesced stores ----------
// 640 blocks x 256 threads: 5 source px per block (p0 = 5q, same hu/hsrc),
// thread = 1 channel. Window 5x9 loaded once; stores staged via smem.
#define ST_STRIDE 24

__global__ void __launch_bounds__(256) stageC_reassemble(float* __restrict__ out) {
    __shared__ float4 sk[5][KK];            // softmax weights per px
    __shared__ float  st[256 * ST_STRIDE];  // [ch][20+pad] output staging

    const int t   = threadIdx.x;
    const int blk = blockIdx.x;
    const int b   = blk / 320;
    const int p0  = (blk % 320) * 5;

    const int hu    = p0 / 20, pm0 = p0 % 20;
    const int hsrc  = p0 / WW, wsrc0 = p0 % WW;   // shared by all 5 px (wsrc_i = wsrc0+i)
    const int wid = t >> 5, lane = t & 31;

    // ---- window loads: 5 rows x 9 cols, all issued up front ----
    const float* xb = &g_xT[((size_t)(b * HPAD + hsrc) * HPAD + wsrc0) * C_IN + t];
    float xw[45];
    #pragma unroll
    for (int r = 0; r < 5; r++)
        #pragma unroll
        for (int c = 0; c < 9; c++)
            xw[r * 9 + c] = xb[(r * HPAD + c) * C_IN];

    // ---- 20 softmaxes (5 px x 4 subpx), 8 warps loop ----
    const int hc = hu >> 1, sh = hu & 1;
    for (int s = wid; s < 20; s += 8) {
        const int px = s >> 2, d = s & 3;
        const int wc = 2 * (pm0 + px) + (d >> 1), sw = d & 1;
        float v = -3.0e38f;
        if (lane < KK)
            v = g_kern[((size_t)(b * HH + hc) * WW + wc) * CK + lane * 4 + sh * 2 + sw];
        float m = v;
        #pragma unroll
        for (int off = 16; off; off >>= 1)
            m = fmaxf(m, __shfl_xor_sync(0xffffffffu, m, off));
        float e = (lane < KK) ? __expf(v - m) : 0.f;
        float su = e;
        #pragma unroll
        for (int off = 16; off; off >>= 1)
            su += __shfl_xor_sync(0xffffffffu, su, off);
        if (lane < KK)
            ((float*)&sk[px][lane])[d] = e / su;
    }
    __syncthreads();

    // ---- per-px FMA, results to staging ----
    #pragma unroll
    for (int i = 0; i < 5; i++) {
        const ulonglong2* skp = (const ulonglong2*)&sk[i][0];
        u64 a01 = 0, a23 = 0;
        #pragma unroll
        for (int k = 0; k < 25; k++) {
            u64 xx = dup2f(xw[(k / 5) * 9 + i + (k % 5)]);
            ulonglong2 w = skp[k];
            fma2(a01, xx, w.x);
            fma2(a23, xx, w.y);
        }
        *(u64*)&st[t * ST_STRIDE + i * 4]     = a01;
        *(u64*)&st[t * ST_STRIDE + i * 4 + 2] = a23;
    }
    __syncthreads();

    // ---- coalesced store: thread = (ch, wu-quad), warp covers consecutive wu ----
    const size_t obase = ((size_t)(b * C_IN) * (2 * HH) + hu) * (2 * WW) + pm0 * 4;
    #pragma unroll
    for (int j = 0; j < 5; j++) {
        int f  = t + j * 256;          // 0..1279
        int ch = f / 5, w4 = f % 5;
        float4 v = *(const float4*)&st[ch * ST_STRIDE + w4 * 4];
        *(float4*)&out[obase + (size_t)ch * (4 * HH * WW) + w4 * 4] = v;
    }
}

// ---------------- launch ----------------
extern "C" void kernel_launch(void* const* d_in, const int* in_sizes, int n_in,
                              void* d_out, int out_size) {
    const float* x     = (const float*)d_in[0];
    const float* wcomp = (const float*)d_in[1];
    const float* wenc  = (const float*)d_in[2];
    float* out = (float*)d_out;

    cudaFuncSetAttribute(stageA_compress,
                         cudaFuncAttributeMaxDynamicSharedMemorySize, SMEM_A_BYTES);
    cudaFuncSetAttribute(stageB_encoder,
                         cudaFuncAttributeMaxDynamicSharedMemorySize, SMEM_B_BYTES);

    stageA_compress<<<100 + (9 * CMID * CK + 255) / 256, 256, SMEM_A_BYTES>>>(x, wcomp, wenc);
    stageB_encoder<<<160, 128, SMEM_B_BYTES>>>();
    stageC_reassemble<<<640, 256>>>(out);
}

// round 12
// speedup vs baseline: 1.3410x; 1.0439x over previous
#include <cuda_runtime.h>
#include <cuda_pipeline.h>

// ---------------- problem dims (fixed by the dataset) ----------------
#define BATCH   2
#define C_IN    256
#define HH      40
#define WW      40
#define CMID    64     // compressed channels
#define CK      100    // k2 * S^2 encoder output channels
#define KK      25     // k2
#define HPAD    44     // xT padded (halo 2)
#define CPH     42     // comp padded (halo 1)

typedef unsigned long long u64;

__device__ __forceinline__ u64 dup2f(float x) {
    u64 r; asm("mov.b64 %0,{%1,%1};" : "=l"(r) : "f"(x)); return r;
}
__device__ __forceinline__ void fma2(u64& d, u64 a, u64 b) {
    asm("fma.rn.f32x2 %0,%1,%2,%0;" : "+l"(d) : "l"(a), "l"(b));
}

// ---------------- scratch (zero-initialized at module load; halos stay 0) ----------------
__device__ __align__(16) float g_xT  [BATCH * HPAD * HPAD * C_IN];   // x NHWC, 2-px zero halo
__device__ __align__(16) float g_comp[BATCH * CPH  * CPH  * CMID];   // compressed NHWC, 1-px halo
__device__ __align__(16) float g_kern[BATCH * HH * WW * CK];         // encoder conv out, NHWC
__device__ __align__(16) float g_wt  [9 * CMID * CK];                // w_enc transposed [tap][ci][o]

// ---------------- stage A: 1x1 GEMM (register-pipelined x chunks) + x transpose + wenc prep ----
// blocks 0..99: GEMM (32 pixels x 64 outputs each). blocks 100..324: wenc transpose.
#define WS_STRIDE 68
#define XS_STRIDE 33
#define SMEM_A_BYTES ((C_IN * WS_STRIDE + 64 * XS_STRIDE) * (int)sizeof(float))

__global__ void stageA_compress(const float* __restrict__ x,
                                const float* __restrict__ wcomp,
                                const float* __restrict__ wenc) {
    extern __shared__ float sm[];
    float* w_s = sm;                       // [c][o] padded stride 68
    float* x_s = sm + C_IN * WS_STRIDE;    // [c_l][pix] padded stride 33

    const int t   = threadIdx.x;
    const int blk = blockIdx.x;

    if (blk >= 100) {                      // w_enc transpose: (100,64,3,3) -> [tap][ci][o]
        int i = (blk - 100) * 256 + t;
        if (i < 9 * CMID * CK) {
            int tap  = i / (CMID * CK);
            int rest = i % (CMID * CK);
            int ci   = rest / CK;
            int o    = rest % CK;
            g_wt[i] = wenc[o * (CMID * 9) + ci * 9 + tap];
        }
        return;
    }

    const int b    = blk / 50;
    const int pix0 = (blk % 50) * 32;

    const int cl_ld = t >> 5;              // channel-local row this thread loads
    const int pl_ld = t & 31;              // pixel-local col this thread loads

    // ---- preload x chunk 0 into registers (latency hides under weight load) ----
    float xr[8];
    #pragma unroll
    for (int r = 0; r < 8; r++)
        xr[r] = x[(size_t)(b * C_IN + 0 + cl_ld + r * 8) * (HH * WW) + pix0 + pl_ld];

    // ---- load all of w_comp (64 x 256), transposed to [c][o] ----
    for (int i = t; i < CMID * C_IN; i += 256) {
        int o = i >> 8, c = i & 255;
        w_s[c * WS_STRIDE + o] = wcomp[i];
    }

    u64 acc[4] = {0ull, 0ull, 0ull, 0ull};
    const int pix_l = t & 31;              // warp spans 32 pixels (x coalesced)
    const int o0    = (t >> 5) << 3;       // warp shares o0 (w broadcast)

    for (int k = 0; k < 4; k++) {
        const int c0 = k * 64;
        __syncthreads();                   // x_s free (prev chunk consumed); iter0: no-op
        // store registers -> x_s
        #pragma unroll
        for (int r = 0; r < 8; r++)
            x_s[(cl_ld + r * 8) * XS_STRIDE + pl_ld] = xr[r];
        __syncthreads();                   // x_s ready (also fences w_s on iter0)

        // issue next chunk's loads NOW — latency hidden behind emit + GEMM below
        if (k < 3) {
            #pragma unroll
            for (int r = 0; r < 8; r++)
                xr[r] = x[(size_t)(b * C_IN + c0 + 64 + cl_ld + r * 8) * (HH * WW) + pix0 + pl_ld];
        }

        // emit transposed x to g_xT (coalesced along channels)
        #pragma unroll
        for (int r = 0; r < 8; r++) {
            int idx = t + r * 256;
            int cl = idx & 63, pl = idx >> 6;
            int pix = pix0 + pl;
            int hs = pix / WW, ws = pix % WW;
            g_xT[((size_t)(b * HPAD + hs + 2) * HPAD + (ws + 2)) * C_IN + c0 + cl] =
                x_s[cl * XS_STRIDE + pl];
        }
        // GEMM chunk
        #pragma unroll 16
        for (int c = 0; c < 64; c++) {
            float xv = x_s[c * XS_STRIDE + pix_l];
            u64 xx = dup2f(xv);
            ulonglong2 wa = *(const ulonglong2*)&w_s[(c0 + c) * WS_STRIDE + o0];
            ulonglong2 wb = *(const ulonglong2*)&w_s[(c0 + c) * WS_STRIDE + o0 + 4];
            fma2(acc[0], xx, wa.x); fma2(acc[1], xx, wa.y);
            fma2(acc[2], xx, wb.x); fma2(acc[3], xx, wb.y);
        }
    }

    const int pix = pix0 + pix_l;
    const int hs = pix / WW, ws = pix % WW;
    float* dst = &g_comp[((size_t)(b * CPH + hs + 1) * CPH + (ws + 1)) * CMID + o0];
    *(ulonglong2*)(dst)     = make_ulonglong2(acc[0], acc[1]);
    *(ulonglong2*)(dst + 4) = make_ulonglong2(acc[2], acc[3]);
}

// ---------------- stage B (R2 verbatim): 3x3 encoder conv (64 -> 100 ch) ----------------
#define CS_STRIDE 66
#define B_WBUF    (CMID * CK)                 // 6400 floats per tap
#define SMEM_B_BYTES ((2 * B_WBUF + 48 * CS_STRIDE) * (int)sizeof(float))

__global__ void __launch_bounds__(128) stageB_encoder() {
    extern __shared__ float smB[];
    float* wbuf   = smB;                       // [2][6400]
    float* comp_s = smB + 2 * B_WBUF;          // [48 px][66]

    const int t   = threadIdx.x;
    const int blk = blockIdx.x;
    const int b   = blk / 80;
    const int rem = blk % 80;
    const int h0  = (rem / 4) * 2;
    const int ws0 = (rem % 4) * 10;

    for (int i = t; i < 48 * CMID; i += 128) {
        int pxl = i >> 6, ci = i & 63;
        comp_s[pxl * CS_STRIDE + ci] =
            g_comp[((size_t)(b * CPH + h0 + pxl / 12) * CPH + ws0 + pxl % 12) * CMID + ci];
    }

    for (int i = t; i < B_WBUF / 4; i += 128)
        __pipeline_memcpy_async(&wbuf[i * 4], &g_wt[i * 4], 16);
    __pipeline_commit();

    const int og  = t / 5;          // 0..24 (t<125 active)
    const int pxg = t % 5;
    const bool active = (t < 125);

    u64 a00 = 0, a01 = 0, a10 = 0, a11 = 0;   // row0 col0/col1: {o0,o1},{o2,o3} packed per px
    u64 b00 = 0, b01 = 0, b10 = 0, b11 = 0;   // row1

    for (int tap = 0; tap < 9; tap++) {
        if (tap < 8) {
            float* dst = &wbuf[((tap + 1) & 1) * B_WBUF];
            const float* src = &g_wt[(tap + 1) * B_WBUF];
            for (int i = t; i < B_WBUF / 4; i += 128)
                __pipeline_memcpy_async(&dst[i * 4], &src[i * 4], 16);
            __pipeline_commit();
            __pipeline_wait_prior(1);
        } else {
            __pipeline_wait_prior(0);
        }
        __syncthreads();

        if (active) {
            const float* ws = &wbuf[(tap & 1) * B_WBUF];
            const int dh = tap / 3, dw = tap % 3;
            const float* p00 = &comp_s[(dh * 12 + 2 * pxg + dw) * CS_STRIDE];
            const float* p01 = p00 + CS_STRIDE;
            const float* p10 = p00 + 12 * CS_STRIDE;
            const float* p11 = p10 + CS_STRIDE;
            #pragma unroll 8
            for (int ci = 0; ci < CMID; ci += 2) {
                float2 x00 = *(const float2*)&p00[ci];
                float2 x01 = *(const float2*)&p01[ci];
                float2 x10 = *(const float2*)&p10[ci];
                float2 x11 = *(const float2*)&p11[ci];
                ulonglong2 w0 = *(const ulonglong2*)&ws[ci * CK + og * 4];
                ulonglong2 w1 = *(const ulonglong2*)&ws[(ci + 1) * CK + og * 4];
                u64 d;
                d = dup2f(x00.x); fma2(a00, d, w0.x); fma2(a01, d, w0.y);
                d = dup2f(x01.x); fma2(a10, d, w0.x); fma2(a11, d, w0.y);
                d = dup2f(x10.x); fma2(b00, d, w0.x); fma2(b01, d, w0.y);
                d = dup2f(x11.x); fma2(b10, d, w0.x); fma2(b11, d, w0.y);
                d = dup2f(x00.y); fma2(a00, d, w1.x); fma2(a01, d, w1.y);
                d = dup2f(x01.y); fma2(a10, d, w1.x); fma2(a11, d, w1.y);
                d = dup2f(x10.y); fma2(b00, d, w1.x); fma2(b01, d, w1.y);
                d = dup2f(x11.y); fma2(b10, d, w1.x); fma2(b11, d, w1.y);
            }
        }
        __syncthreads();
    }

    if (active) {
        const int c0 = ws0 + 2 * pxg;
        float* r0 = &g_kern[((size_t)(b * HH + h0) * WW + c0) * CK + og * 4];
        float* r1 = &g_kern[((size_t)(b * HH + h0 + 1) * WW + c0) * CK + og * 4];
        *(ulonglong2*)(r0)      = make_ulonglong2(a00, a01);
        *(ulonglong2*)(r0 + CK) = make_ulonglong2(a10, a11);
        *(ulonglong2*)(r1)      = make_ulonglong2(b00, b01);
        *(ulonglong2*)(r1 + CK) = make_ulonglong2(b10, b11);
    }
}

// ---------------- stage C (R7 verbatim): sliding-window reassembly, coalesced stores ----------
#define ST_STRIDE 24

__global__ void __launch_bounds__(256) stageC_reassemble(float* __restrict__ out) {
    __shared__ float4 sk[5][KK];            // softmax weights per px
    __shared__ float  st[256 * ST_STRIDE];  // [ch][20+pad] output staging

    const int t   = threadIdx.x;
    const int blk = blockIdx.x;
    const int b   = blk / 320;
    const int p0  = (blk % 320) * 5;

    const int hu    = p0 / 20, pm0 = p0 % 20;
    const int hsrc  = p0 / WW, wsrc0 = p0 % WW;   // shared by all 5 px (wsrc_i = wsrc0+i)
    const int wid = t >> 5, lane = t & 31;

    // ---- window loads: 5 rows x 9 cols, all issued up front ----
    const float* xb = &g_xT[((size_t)(b * HPAD + hsrc) * HPAD + wsrc0) * C_IN + t];
    float xw[45];
    #pragma unroll
    for (int r = 0; r < 5; r++)
        #pragma unroll
        for (int c = 0; c < 9; c++)
            xw[r * 9 + c] = xb[(r * HPAD + c) * C_IN];

    // ---- 20 softmaxes (5 px x 4 subpx), 8 warps loop ----
    const int hc = hu >> 1, sh = hu & 1;
    for (int s = wid; s < 20; s += 8) {
        const int px = s >> 2, d = s & 3;
        const int wc = 2 * (pm0 + px) + (d >> 1), sw = d & 1;
        float v = -3.0e38f;
        if (lane < KK)
            v = g_kern[((size_t)(b * HH + hc) * WW + wc) * CK + lane * 4 + sh * 2 + sw];
        float m = v;
        #pragma unroll
        for (int off = 16; off; off >>= 1)
            m = fmaxf(m, __shfl_xor_sync(0xffffffffu, m, off));
        float e = (lane < KK) ? __expf(v - m) : 0.f;
        float su = e;
        #pragma unroll
        for (int off = 16; off; off >>= 1)
            su += __shfl_xor_sync(0xffffffffu, su, off);
        if (lane < KK)
            ((float*)&sk[px][lane])[d] = e / su;
    }
    __syncthreads();

    // ---- per-px FMA, results to staging ----
    #pragma unroll
    for (int i = 0; i < 5; i++) {
        const ulonglong2* skp = (const ulonglong2*)&sk[i][0];
        u64 a01 = 0, a23 = 0;
        #pragma unroll
        for (int k = 0; k < 25; k++) {
            u64 xx = dup2f(xw[(k / 5) * 9 + i + (k % 5)]);
            ulonglong2 w = skp[k];
            fma2(a01, xx, w.x);
            fma2(a23, xx, w.y);
        }
        *(u64*)&st[t * ST_STRIDE + i * 4]     = a01;
        *(u64*)&st[t * ST_STRIDE + i * 4 + 2] = a23;
    }
    __syncthreads();

    // ---- coalesced store: thread = (ch, wu-quad), warp covers consecutive wu ----
    const size_t obase = ((size_t)(b * C_IN) * (2 * HH) + hu) * (2 * WW) + pm0 * 4;
    #pragma unroll
    for (int j = 0; j < 5; j++) {
        int f  = t + j * 256;          // 0..1279
        int ch = f / 5, w4 = f % 5;
        float4 v = *(const float4*)&st[ch * ST_STRIDE + w4 * 4];
        *(float4*)&out[obase + (size_t)ch * (4 * HH * WW) + w4 * 4] = v;
    }
}

// ---------------- launch ----------------
extern "C" void kernel_launch(void* const* d_in, const int* in_sizes, int n_in,
                              void* d_out, int out_size) {
    const float* x     = (const float*)d_in[0];
    const float* wcomp = (const float*)d_in[1];
    const float* wenc  = (const float*)d_in[2];
    float* out = (float*)d_out;

    cudaFuncSetAttribute(stageA_compress,
                         cudaFuncAttributeMaxDynamicSharedMemorySize, SMEM_A_BYTES);
    cudaFuncSetAttribute(stageB_encoder,
                         cudaFuncAttributeMaxDynamicSharedMemorySize, SMEM_B_BYTES);

    stageA_compress<<<100 + (9 * CMID * CK + 255) / 256, 256, SMEM_A_BYTES>>>(x, wcomp, wenc);
    stageB_encoder<<<160, 128, SMEM_B_BYTES>>>();
    stageC_reassemble<<<640, 256>>>(out);
}